// round 1
// baseline (speedup 1.0000x reference)
#include <cuda_runtime.h>
#include <math.h>

#define Bc 16
#define Lc 128
#define Dc 8
#define Hc 128
#define NLc 2

// ---------------- scratch (static device globals; no allocation) ----------------
__device__ float g_ts[Bc*Lc];
__device__ float g_h[Bc*Lc*Hc];
__device__ float g_sa[Bc*Lc*Hc];
__device__ float g_da[Bc*Lc*Hc];
__device__ float g_sm[Bc*Lc*Hc];
__device__ float g_aggpre[Bc*Lc*Hc];
__device__ float g_Wca[NLc*Hc*Hc];
__device__ float g_Wcm[NLc*Hc*Hc];
__device__ float g_ba[NLc*Hc];
__device__ float g_bm[NLc*Hc];

// ---------------- packed f32x2 helpers ----------------
__device__ __forceinline__ void fma2(unsigned long long &acc, unsigned long long a, unsigned long long b){
    asm("fma.rn.f32x2 %0, %1, %2, %0;" : "+l"(acc) : "l"(a), "l"(b));
}
__device__ __forceinline__ unsigned long long pack2(float lo, float hi){
    unsigned long long r; asm("mov.b64 %0, {%1,%2};" : "=l"(r) : "f"(lo), "f"(hi)); return r;
}
__device__ __forceinline__ void unpack2(unsigned long long v, float &lo, float &hi){
    asm("mov.b64 {%0,%1}, %2;" : "=f"(lo), "=f"(hi) : "l"(v));
}

// ---------------- tiny kernels ----------------
__global__ void k_ts(const float* __restrict__ hist){
    int b = threadIdx.x;
    if(b < Bc){
        float c = 0.f;
        for(int t = 0; t < Lc; t++){
            float v = hist[(b*Lc+t)*Dc + 5];
            c += fmaxf(v, 0.f);
            g_ts[b*Lc+t] = c;
        }
    }
}

__global__ void k_h0(const float* __restrict__ hist, const float* __restrict__ mask,
                     const float* __restrict__ Wp, const float* __restrict__ bp){
    int row = blockIdx.x; int c = threadIdx.x;
    __shared__ float xs[Dc];
    if(threadIdx.x < Dc) xs[threadIdx.x] = hist[row*Dc + threadIdx.x];
    __syncthreads();
    float a = bp[c];
    #pragma unroll
    for(int d = 0; d < Dc; d++) a += xs[d] * Wp[d*Hc + c];
    float vm = mask[row] > 0.f ? 1.f : 0.f;
    g_h[row*Hc + c] = a * vm;
}

// Wc_a[l][k][c] = sum_r We2[l][k][r]*Wa1[l][2H+r][c];  Wc_m with Wm1[l][H+r][c]
__global__ void k_prepw(const float* __restrict__ We2, const float* __restrict__ Wa1,
                        const float* __restrict__ Wm1){
    int l = blockIdx.x >> 7, k = blockIdx.x & 127, c = threadIdx.x;
    __shared__ float ws[Hc];
    ws[c] = We2[l*Hc*Hc + k*Hc + c];
    __syncthreads();
    const float* wa = Wa1 + l*3*Hc*Hc + 2*Hc*Hc;
    const float* wm = Wm1 + l*2*Hc*Hc + Hc*Hc;
    float sa = 0.f, sm = 0.f;
    for(int r = 0; r < Hc; r++){ float w = ws[r]; sa += w*wa[r*Hc + c]; sm += w*wm[r*Hc + c]; }
    g_Wca[(l*Hc + k)*Hc + c] = sa;
    g_Wcm[(l*Hc + k)*Hc + c] = sm;
}

__global__ void k_prepb(const float* __restrict__ be2, const float* __restrict__ Wa1,
                        const float* __restrict__ Wm1, const float* __restrict__ ba1,
                        const float* __restrict__ bm1){
    int l = blockIdx.x, c = threadIdx.x;
    const float* wa = Wa1 + l*3*Hc*Hc + 2*Hc*Hc;
    const float* wm = Wm1 + l*2*Hc*Hc + Hc*Hc;
    const float* b2 = be2 + l*Hc;
    float sa = ba1[l*Hc + c], sm = bm1[l*Hc + c];
    for(int r = 0; r < Hc; r++){ float w = b2[r]; sa += w*wa[r*Hc + c]; sm += w*wm[r*Hc + c]; }
    g_ba[l*Hc + c] = sa;
    g_bm[l*Hc + c] = sm;
}

// sa = h@Wa1[:H], da = h@Wa1[H:2H], sm = h@Wm1[:H]
__global__ void k_sadam(int l, const float* __restrict__ Wa1, const float* __restrict__ Wm1){
    int row = blockIdx.x, c = threadIdx.x;
    __shared__ float hs[Hc];
    hs[c] = g_h[row*Hc + c];
    __syncthreads();
    const float* was = Wa1 + l*3*Hc*Hc;
    const float* wad = was + Hc*Hc;
    const float* wms = Wm1 + l*2*Hc*Hc;
    float a = 0.f, d = 0.f, m = 0.f;
    for(int k = 0; k < Hc; k++){
        float h = hs[k];
        a += h*was[k*Hc + c];
        d += h*wad[k*Hc + c];
        m += h*wms[k*Hc + c];
    }
    g_sa[row*Hc + c] = a; g_da[row*Hc + c] = d; g_sm[row*Hc + c] = m;
}

// ---------------- main fused edge/attention/message kernel ----------------
// one block per (b,i); 256 threads; ty=tid>>4 (j-tiles of 4 within 64-j half), tx=tid&15 (8 c)
__device__ __forceinline__ void gemm_tile(const float* __restrict__ Wg, const float* Ts,
                                          float* Wt, int tid, unsigned long long acc[4][4]){
    int tx = tid & 15, ty = tid >> 4;
    int c0 = tx*8, jt = ty*4;
    #pragma unroll
    for(int r = 0; r < 4; r++)
        #pragma unroll
        for(int p = 0; p < 4; p++) acc[r][p] = 0ull;
    for(int k0 = 0; k0 < Hc; k0 += 16){
        __syncthreads();
        #pragma unroll
        for(int m = 0; m < 8; m++){ int idx = m*256 + tid; Wt[idx] = Wg[k0*Hc + idx]; }
        __syncthreads();
        #pragma unroll
        for(int kk = 0; kk < 16; kk++){
            const float* wrow = &Wt[kk*Hc + c0];
            float4 f0 = *(const float4*)wrow;
            float4 f1 = *(const float4*)(wrow + 4);
            unsigned long long wp0 = pack2(f0.x, f0.y), wp1 = pack2(f0.z, f0.w);
            unsigned long long wp2 = pack2(f1.x, f1.y), wp3 = pack2(f1.z, f1.w);
            #pragma unroll
            for(int r = 0; r < 4; r++){
                float tv = Ts[(jt + r)*Hc + k0 + kk];
                unsigned long long tp = pack2(tv, tv);
                fma2(acc[r][0], tp, wp0);
                fma2(acc[r][1], tp, wp1);
                fma2(acc[r][2], tp, wp2);
                fma2(acc[r][3], tp, wp3);
            }
        }
    }
    __syncthreads();
}

__global__ __launch_bounds__(256, 2)
void k_main(int l, const float* __restrict__ hist, const float* __restrict__ mask,
            const float* __restrict__ We1, const float* __restrict__ be1,
            const float* __restrict__ wa2, const float* __restrict__ ba2){
    int bi = blockIdx.x;
    int b = bi >> 7, i = bi & 127;
    int tid = threadIdx.x;

    __shared__ float Ts[64*Hc];          // 32 KB (half of j)
    __shared__ float su[16*Hc];          // 8 KB: W tile / agg partials (time-shared)
    __shared__ float e_dist[Lc], e_dt[Lc], e_ss[Lc], e_vld[Lc];
    __shared__ float sab[Hc], smb[Hc], wa2s[Hc], att[Lc], wsoft[Lc];
    __shared__ float red2[8];

    const float* hb_ = hist + (size_t)b*Lc*Dc;
    float lat_i = hb_[i*Dc + 0], lon_i = hb_[i*Dc + 1], src_i = hb_[i*Dc + 6];
    float ts_i = g_ts[b*Lc + i];

    if(tid < 128){
        int j = tid;
        float latj = hb_[j*Dc + 0], lonj = hb_[j*Dc + 1], srcj = hb_[j*Dc + 6];
        float tsj = g_ts[b*Lc + j];
        float dl = lat_i - latj, dn = lon_i - lonj;
        e_dist[j] = sqrtf(dl*dl + dn*dn + 1e-8f);
        e_dt[j]   = fabsf(ts_i - tsj) * (1.f/300.f);
        e_ss[j]   = (src_i == srcj) ? 1.f : 0.f;
        e_vld[j]  = (mask[b*Lc + j] > 0.f) ? 1.f : 0.f;
        sab[j]  = g_sa[bi*Hc + j] + g_ba[l*Hc + j];
        smb[j]  = g_sm[bi*Hc + j] + g_bm[l*Hc + j];
        wa2s[j] = wa2[l*Hc + j];
    }
    __syncthreads();

    // per-thread T-build params: fixed k-column, two j-interleave groups
    int kb = tid & 127, jg = tid >> 7;
    const float* we1 = We1 + l*4*Hc;
    float w0 = we1[0*Hc + kb], w1 = we1[1*Hc + kb], w2 = we1[2*Hc + kb], w3 = we1[3*Hc + kb];
    float bb = be1[l*Hc + kb];

    int tx = tid & 15, ty = tid >> 4;
    int c0 = tx*8, jt = ty*4;
    unsigned long long acc[4][4];
    const float inv = 0.088388347648318440550f;   // 1/sqrt(128)

    // ---------------- attention phase ----------------
    for(int jh = 0; jh < 2; jh++){
        // build T half
        #pragma unroll 4
        for(int jj = 0; jj < 32; jj++){
            int jloc = jj*2 + jg, j = jh*64 + jloc;
            float v = e_dist[j]*w0 + e_dt[j]*w1 + e_ss[j]*w2 + ((j == i) ? w3 : 0.f) + bb;
            Ts[jloc*Hc + kb] = fmaxf(v, 0.f);
        }
        __syncthreads();
        gemm_tile(g_Wca + l*Hc*Hc, Ts, su, tid, acc);
        #pragma unroll
        for(int r = 0; r < 4; r++){
            int j = jh*64 + jt + r;
            const float4* dar = (const float4*)&g_da[((size_t)b*Lc + j)*Hc + c0];
            float4 d0 = dar[0], d1 = dar[1];
            float a0,a1,a2,a3,a4,a5,a6,a7;
            unpack2(acc[r][0], a0, a1); unpack2(acc[r][1], a2, a3);
            unpack2(acc[r][2], a4, a5); unpack2(acc[r][3], a6, a7);
            float pr = 0.f;
            pr += wa2s[c0+0]*tanhf(sab[c0+0] + d0.x + a0);
            pr += wa2s[c0+1]*tanhf(sab[c0+1] + d0.y + a1);
            pr += wa2s[c0+2]*tanhf(sab[c0+2] + d0.z + a2);
            pr += wa2s[c0+3]*tanhf(sab[c0+3] + d0.w + a3);
            pr += wa2s[c0+4]*tanhf(sab[c0+4] + d1.x + a4);
            pr += wa2s[c0+5]*tanhf(sab[c0+5] + d1.y + a5);
            pr += wa2s[c0+6]*tanhf(sab[c0+6] + d1.z + a6);
            pr += wa2s[c0+7]*tanhf(sab[c0+7] + d1.w + a7);
            #pragma unroll
            for(int s = 8; s > 0; s >>= 1) pr += __shfl_xor_sync(0xffffffffu, pr, s);
            if(tx == 0) att[j] = pr;
        }
        __syncthreads();
    }

    // ---------------- softmax over j ----------------
    float vi = e_vld[i];
    if(tid < 128){
        float a = (att[tid] + ba2[l]) * inv;
        bool ok = (e_vld[tid] > 0.f) && (vi > 0.f);
        att[tid] = ok ? a : -1e9f;
    }
    __syncthreads();
    {
        float m = (tid < 128) ? att[tid] : -INFINITY;
        #pragma unroll
        for(int s = 16; s > 0; s >>= 1) m = fmaxf(m, __shfl_xor_sync(0xffffffffu, m, s));
        if((tid & 31) == 0) red2[tid >> 5] = m;
        __syncthreads();
        float bm = red2[0];
        #pragma unroll
        for(int q = 1; q < 8; q++) bm = fmaxf(bm, red2[q]);
        float e = 0.f;
        if(tid < 128){ e = expf(att[tid] - bm); }
        float s2 = e;
        #pragma unroll
        for(int s = 16; s > 0; s >>= 1) s2 += __shfl_xor_sync(0xffffffffu, s2, s);
        __syncthreads();
        if((tid & 31) == 0) red2[tid >> 5] = s2;
        __syncthreads();
        float tot = red2[0]+red2[1]+red2[2]+red2[3]+red2[4]+red2[5]+red2[6]+red2[7];
        if(tid < 128) wsoft[tid] = e / tot;
    }
    __syncthreads();

    // ---------------- message phase ----------------
    float aggacc[8];
    #pragma unroll
    for(int p = 0; p < 8; p++) aggacc[p] = 0.f;

    for(int jh = 0; jh < 2; jh++){
        #pragma unroll 4
        for(int jj = 0; jj < 32; jj++){
            int jloc = jj*2 + jg, j = jh*64 + jloc;
            float v = e_dist[j]*w0 + e_dt[j]*w1 + e_ss[j]*w2 + ((j == i) ? w3 : 0.f) + bb;
            Ts[jloc*Hc + kb] = fmaxf(v, 0.f);
        }
        __syncthreads();
        gemm_tile(g_Wcm + l*Hc*Hc, Ts, su, tid, acc);
        #pragma unroll
        for(int r = 0; r < 4; r++){
            int j = jh*64 + jt + r;
            float wj = wsoft[j];
            float a0,a1,a2,a3,a4,a5,a6,a7;
            unpack2(acc[r][0], a0, a1); unpack2(acc[r][1], a2, a3);
            unpack2(acc[r][2], a4, a5); unpack2(acc[r][3], a6, a7);
            aggacc[0] += wj * fmaxf(smb[c0+0] + a0, 0.f);
            aggacc[1] += wj * fmaxf(smb[c0+1] + a1, 0.f);
            aggacc[2] += wj * fmaxf(smb[c0+2] + a2, 0.f);
            aggacc[3] += wj * fmaxf(smb[c0+3] + a3, 0.f);
            aggacc[4] += wj * fmaxf(smb[c0+4] + a4, 0.f);
            aggacc[5] += wj * fmaxf(smb[c0+5] + a5, 0.f);
            aggacc[6] += wj * fmaxf(smb[c0+6] + a6, 0.f);
            aggacc[7] += wj * fmaxf(smb[c0+7] + a7, 0.f);
        }
        __syncthreads();
    }
    // reduce across the 16 j-tile groups
    #pragma unroll
    for(int p = 0; p < 8; p++) su[ty*Hc + c0 + p] = aggacc[p];
    __syncthreads();
    if(tid < 128){
        float s = 0.f;
        #pragma unroll
        for(int t = 0; t < 16; t++) s += su[t*Hc + tid];
        g_aggpre[bi*Hc + tid] = s;
    }
}

// ---------------- per-node epilogue: agg@Wm2, out-MLP, residual + LN ----------------
__global__ void k_post(int l, const float* __restrict__ mask,
                       const float* __restrict__ Wm2, const float* __restrict__ bm2,
                       const float* __restrict__ Wo1, const float* __restrict__ bo1,
                       const float* __restrict__ Wo2, const float* __restrict__ bo2,
                       const float* __restrict__ lng, const float* __restrict__ lnb){
    int row = blockIdx.x; int c = threadIdx.x;
    __shared__ float hr[Hc], ar[Hc], agg[Hc], op1[Hc];
    __shared__ float red2[4];
    hr[c] = g_h[row*Hc + c];
    ar[c] = g_aggpre[row*Hc + c];
    __syncthreads();
    const float* wm2 = Wm2 + l*Hc*Hc;
    float s = bm2[l*Hc + c];
    for(int k = 0; k < Hc; k++) s += ar[k]*wm2[k*Hc + c];
    agg[c] = s;
    __syncthreads();
    const float* wo1h = Wo1 + l*2*Hc*Hc;
    const float* wo1a = wo1h + Hc*Hc;
    float t = bo1[l*Hc + c];
    for(int k = 0; k < Hc; k++) t += hr[k]*wo1h[k*Hc + c] + agg[k]*wo1a[k*Hc + c];
    op1[c] = fmaxf(t, 0.f);
    __syncthreads();
    const float* wo2 = Wo2 + l*Hc*Hc;
    float o = bo2[l*Hc + c];
    for(int k = 0; k < Hc; k++) o += op1[k]*wo2[k*Hc + c];
    float x = hr[c] + o;
    // layer norm over 128
    float m = x;
    #pragma unroll
    for(int sft = 16; sft > 0; sft >>= 1) m += __shfl_xor_sync(0xffffffffu, m, sft);
    if((c & 31) == 0) red2[c >> 5] = m;
    __syncthreads();
    float mu = (red2[0]+red2[1]+red2[2]+red2[3]) * (1.f/128.f);
    float d = x - mu;
    float v = d*d;
    #pragma unroll
    for(int sft = 16; sft > 0; sft >>= 1) v += __shfl_xor_sync(0xffffffffu, v, sft);
    __syncthreads();
    if((c & 31) == 0) red2[c >> 5] = v;
    __syncthreads();
    float var = (red2[0]+red2[1]+red2[2]+red2[3]) * (1.f/128.f);
    float vm = mask[row] > 0.f ? 1.f : 0.f;
    g_h[row*Hc + c] = (d * rsqrtf(var + 1e-5f) * lng[l*Hc + c] + lnb[l*Hc + c]) * vm;
}

// ---------------- decoder ----------------
__global__ void k_dec(const float* __restrict__ hist, const float* __restrict__ mask,
                      const float* __restrict__ hg, const float* __restrict__ hb,
                      const float* __restrict__ Wh1, const float* __restrict__ bh1,
                      const float* __restrict__ Wh2, const float* __restrict__ bh2,
                      float* __restrict__ out){
    int b = blockIdx.x; int t = threadIdx.x;
    __shared__ float x[136], xn[136], hid[Hc];
    __shared__ float red2[4];
    // sum of mask -> last valid index
    float mv = mask[b*Lc + t];
    float s = mv;
    #pragma unroll
    for(int sft = 16; sft > 0; sft >>= 1) s += __shfl_xor_sync(0xffffffffu, s, sft);
    if((t & 31) == 0) red2[t >> 5] = s;
    __syncthreads();
    float tot = red2[0]+red2[1]+red2[2]+red2[3];
    int vc = (int)tot;
    vc = min(max(vc, 1), Lc);
    int last = vc - 1;

    if(t < Dc) x[t] = hist[((size_t)b*Lc + last)*Dc + t];
    x[Dc + t] = g_h[((size_t)b*Lc + last)*Hc + t];
    __syncthreads();
    // LN over 136: thread t owns element t, and t<8 also owns 128+t
    float s1 = x[t] + ((t < 8) ? x[128 + t] : 0.f);
    #pragma unroll
    for(int sft = 16; sft > 0; sft >>= 1) s1 += __shfl_xor_sync(0xffffffffu, s1, sft);
    __syncthreads();
    if((t & 31) == 0) red2[t >> 5] = s1;
    __syncthreads();
    float mu = (red2[0]+red2[1]+red2[2]+red2[3]) * (1.f/136.f);
    float d0 = x[t] - mu;
    float s2 = d0*d0;
    if(t < 8){ float d1 = x[128 + t] - mu; s2 += d1*d1; }
    #pragma unroll
    for(int sft = 16; sft > 0; sft >>= 1) s2 += __shfl_xor_sync(0xffffffffu, s2, sft);
    __syncthreads();
    if((t & 31) == 0) red2[t >> 5] = s2;
    __syncthreads();
    float rs = rsqrtf((red2[0]+red2[1]+red2[2]+red2[3]) * (1.f/136.f) + 1e-5f);
    xn[t] = (x[t] - mu) * rs * hg[t] + hb[t];
    if(t < 8) xn[128 + t] = (x[128 + t] - mu) * rs * hg[128 + t] + hb[128 + t];
    __syncthreads();
    float h_ = bh1[t];
    for(int k = 0; k < 136; k++) h_ += xn[k]*Wh1[k*Hc + t];
    hid[t] = fmaxf(h_, 0.f);
    __syncthreads();
    if(t < 24){
        float p = bh2[t];
        for(int k = 0; k < Hc; k++) p += hid[k]*Wh2[k*24 + t];
        if(isnan(p)) p = 0.f;
        else if(isinf(p)) p = (p > 0.f) ? 1e4f : -1e4f;
        out[b*24 + t] = p;
    }
}

__global__ void k_copyh(float* __restrict__ out){
    int i = blockIdx.x*blockDim.x + threadIdx.x;
    out[384 + i] = g_h[i];
}

// ---------------- launch ----------------
extern "C" void kernel_launch(void* const* d_in, const int* in_sizes, int n_in,
                              void* d_out, int out_size){
    const float* hist = (const float*)d_in[0];
    const float* mask = (const float*)d_in[1];
    const float* Wp   = (const float*)d_in[2];
    const float* bp   = (const float*)d_in[3];
    const float* We1  = (const float*)d_in[4];
    const float* be1  = (const float*)d_in[5];
    const float* We2  = (const float*)d_in[6];
    const float* be2  = (const float*)d_in[7];
    const float* Wa1  = (const float*)d_in[8];
    const float* ba1  = (const float*)d_in[9];
    const float* wa2  = (const float*)d_in[10];
    const float* ba2  = (const float*)d_in[11];
    const float* Wm1  = (const float*)d_in[12];
    const float* bm1  = (const float*)d_in[13];
    const float* Wm2  = (const float*)d_in[14];
    const float* bm2  = (const float*)d_in[15];
    const float* Wo1  = (const float*)d_in[16];
    const float* bo1  = (const float*)d_in[17];
    const float* Wo2  = (const float*)d_in[18];
    const float* bo2  = (const float*)d_in[19];
    const float* lng  = (const float*)d_in[20];
    const float* lnb  = (const float*)d_in[21];
    const float* hg   = (const float*)d_in[22];
    const float* hbv  = (const float*)d_in[23];
    const float* Wh1  = (const float*)d_in[24];
    const float* bh1  = (const float*)d_in[25];
    const float* Wh2  = (const float*)d_in[26];
    const float* bh2  = (const float*)d_in[27];
    float* out = (float*)d_out;

    k_ts<<<1, 32>>>(hist);
    k_h0<<<Bc*Lc, Hc>>>(hist, mask, Wp, bp);
    k_prepw<<<NLc*Hc, Hc>>>(We2, Wa1, Wm1);
    k_prepb<<<NLc, Hc>>>(be2, Wa1, Wm1, ba1, bm1);
    for(int l = 0; l < NLc; l++){
        k_sadam<<<Bc*Lc, Hc>>>(l, Wa1, Wm1);
        k_main<<<Bc*Lc, 256>>>(l, hist, mask, We1, be1, wa2, ba2);
        k_post<<<Bc*Lc, Hc>>>(l, mask, Wm2, bm2, Wo1, bo1, Wo2, bo2, lng, lnb);
    }
    k_dec<<<Bc, Hc>>>(hist, mask, hg, hbv, Wh1, bh1, Wh2, bh2, out);
    if(out_size >= 384 + Bc*Lc*Hc){
        k_copyh<<<(Bc*Lc*Hc)/256, 256>>>(out);
    }
}

// round 2
// speedup vs baseline: 1.1285x; 1.1285x over previous
#include <cuda_runtime.h>
#include <math.h>

#define Bc 16
#define Lc 128
#define Dc 8
#define Hc 128
#define NLc 2

// ---------------- scratch (static device globals; no allocation) ----------------
__device__ __align__(16) float g_ts[Bc*Lc];
__device__ __align__(16) float g_h[Bc*Lc*Hc];
__device__ __align__(16) float g_sa[Bc*Lc*Hc];
__device__ __align__(16) float g_da[Bc*Lc*Hc];
__device__ __align__(16) float g_sm[Bc*Lc*Hc];
__device__ __align__(16) float g_aggpre[Bc*Lc*Hc];
__device__ __align__(16) float g_Wca[NLc*Hc*Hc];
__device__ __align__(16) float g_Wcm[NLc*Hc*Hc];
__device__ __align__(16) float g_ba[NLc*Hc];
__device__ __align__(16) float g_bm[NLc*Hc];

// ---------------- packed f32x2 helpers ----------------
__device__ __forceinline__ void fma2(unsigned long long &acc, unsigned long long a, unsigned long long b){
    asm("fma.rn.f32x2 %0, %1, %2, %0;" : "+l"(acc) : "l"(a), "l"(b));
}
__device__ __forceinline__ unsigned long long pack2(float lo, float hi){
    unsigned long long r; asm("mov.b64 %0, {%1,%2};" : "=l"(r) : "f"(lo), "f"(hi)); return r;
}
__device__ __forceinline__ void unpack2(unsigned long long v, float &lo, float &hi){
    asm("mov.b64 {%0,%1}, %2;" : "=f"(lo), "=f"(hi) : "l"(v));
}
__device__ __forceinline__ void cp16(void* dst_smem, const void* src){
    unsigned sdst = (unsigned)__cvta_generic_to_shared(dst_smem);
    asm volatile("cp.async.cg.shared.global [%0], [%1], 16;" :: "r"(sdst), "l"(src));
}

// ---------------- cumsum of ts ----------------
__global__ void k_ts(const float* __restrict__ hist){
    int b = threadIdx.x;
    if(b < Bc){
        float c = 0.f;
        for(int t = 0; t < Lc; t++){
            float v = hist[(b*Lc+t)*Dc + 5];
            c += fmaxf(v, 0.f);
            g_ts[b*Lc+t] = c;
        }
    }
}

// ---------------- folded weights: Wc = We2 @ Wa1_e / Wm1_e (plus bias rows) ----------------
__global__ void k_prepwb(const float* __restrict__ We2, const float* __restrict__ be2,
                         const float* __restrict__ Wa1, const float* __restrict__ Wm1,
                         const float* __restrict__ ba1, const float* __restrict__ bm1){
    int l = blockIdx.x / 129, kk = blockIdx.x % 129;
    int c = threadIdx.x;
    __shared__ float ws[Hc];
    if(kk < Hc) ws[c] = We2[l*Hc*Hc + kk*Hc + c];
    else        ws[c] = be2[l*Hc + c];
    __syncthreads();
    const float* wa = Wa1 + l*3*Hc*Hc + 2*Hc*Hc;
    const float* wm = Wm1 + l*2*Hc*Hc + Hc*Hc;
    float sa = 0.f, sm = 0.f;
    #pragma unroll 4
    for(int r = 0; r < Hc; r++){ float w = ws[r]; sa += w*wa[r*Hc + c]; sm += w*wm[r*Hc + c]; }
    if(kk < Hc){
        g_Wca[(l*Hc + kk)*Hc + c] = sa;
        g_Wcm[(l*Hc + kk)*Hc + c] = sm;
    } else {
        g_ba[l*Hc + c] = sa + ba1[l*Hc + c];
        g_bm[l*Hc + c] = sm + bm1[l*Hc + c];
    }
}

// ---------------- h0 (16 rows per block) + sa/da/sm for layer 0 ----------------
__global__ __launch_bounds__(256)
void k_h0s(const float* __restrict__ hist, const float* __restrict__ mask,
           const float* __restrict__ Wp, const float* __restrict__ bp,
           const float* __restrict__ Wa1, const float* __restrict__ Wm1){
    int row0 = blockIdx.x * 16;
    int tid = threadIdx.x;
    int c = tid & 127, ty = tid >> 7;
    __shared__ float xs[16*Dc], hs[16*Hc], vmsh[16];
    if(tid < 128) xs[tid] = hist[(size_t)row0*Dc + tid];
    if(tid < 16)  vmsh[tid] = mask[row0 + tid] > 0.f ? 1.f : 0.f;
    __syncthreads();
    float acc[8];
    #pragma unroll
    for(int p = 0; p < 8; p++) acc[p] = bp[c];
    #pragma unroll
    for(int d = 0; d < Dc; d++){
        float w = Wp[d*Hc + c];
        #pragma unroll
        for(int p = 0; p < 8; p++) acc[p] += xs[(ty*8+p)*Dc + d] * w;
    }
    #pragma unroll
    for(int p = 0; p < 8; p++){
        int r = ty*8 + p;
        float h = acc[p] * vmsh[r];
        hs[r*Hc + c] = h;
        g_h[(size_t)(row0+r)*Hc + c] = h;
    }
    __syncthreads();
    // sa/da/sm for layer 0
    const float* was = Wa1;              // l=0
    const float* wad = was + Hc*Hc;
    const float* wms = Wm1;
    float aa[8], dd[8], mm[8];
    #pragma unroll
    for(int p = 0; p < 8; p++){ aa[p]=0.f; dd[p]=0.f; mm[p]=0.f; }
    #pragma unroll 4
    for(int k = 0; k < Hc; k++){
        float w1 = was[k*Hc + c], w2 = wad[k*Hc + c], w3 = wms[k*Hc + c];
        #pragma unroll
        for(int p = 0; p < 8; p++){
            float h = hs[(ty*8+p)*Hc + k];
            aa[p] += h*w1; dd[p] += h*w2; mm[p] += h*w3;
        }
    }
    #pragma unroll
    for(int p = 0; p < 8; p++){
        size_t r = (size_t)(row0 + ty*8 + p)*Hc + c;
        g_sa[r] = aa[p]; g_da[r] = dd[p]; g_sm[r] = mm[p];
    }
}

// ---------------- main fused kernel: T build + 2 GEMMs + att + softmax + msg agg ----------------
extern __shared__ float dsm[];   // Ts 64KB | Wa 64KB | Wm 64KB

__global__ __launch_bounds__(512, 1)
void k_main2(int l, const float* __restrict__ hist, const float* __restrict__ mask,
             const float* __restrict__ We1, const float* __restrict__ be1,
             const float* __restrict__ wa2, const float* __restrict__ ba2){
    float* Ts = dsm;                 // [k][j]
    float* Wa = dsm + 16384;         // [k][c]
    float* Wm = dsm + 32768;         // [k][c]
    __shared__ float we1s[4*Hc], be1s[Hc], sab[Hc], smb[Hc], wa2s[Hc];
    __shared__ float att[Lc], wsoft[Lc], red[8];

    int bi = blockIdx.x;
    int b = bi >> 7, i = bi & 127;
    int tid = threadIdx.x;
    int j = tid & 127, g = tid >> 7;

    // start async copy of both folded W matrices
    const float* gwa = g_Wca + l*Hc*Hc;
    const float* gwm = g_Wcm + l*Hc*Hc;
    #pragma unroll
    for(int q = 0; q < 8; q++){
        cp16(Wa + q*2048 + tid*4, gwa + q*2048 + tid*4);
        cp16(Wm + q*2048 + tid*4, gwm + q*2048 + tid*4);
    }
    asm volatile("cp.async.commit_group;");

    if(tid < 128){
        #pragma unroll
        for(int q = 0; q < 4; q++) we1s[q*Hc + tid] = We1[l*4*Hc + q*Hc + tid];
        be1s[tid] = be1[l*Hc + tid];
        sab[tid]  = g_sa[(size_t)bi*Hc + tid] + g_ba[l*Hc + tid];
        smb[tid]  = g_sm[(size_t)bi*Hc + tid] + g_bm[l*Hc + tid];
        wa2s[tid] = wa2[l*Hc + tid];
    }

    // edge features for this thread's j
    const float* hb_ = hist + (size_t)b*Lc*Dc;
    float lat_i = hb_[i*Dc + 0], lon_i = hb_[i*Dc + 1], src_i = hb_[i*Dc + 6];
    float ts_i = g_ts[b*Lc + i];
    float latj = hb_[j*Dc + 0], lonj = hb_[j*Dc + 1], srcj = hb_[j*Dc + 6];
    float tsj = g_ts[b*Lc + j];
    float dl = lat_i - latj, dn = lon_i - lonj;
    float dist = sqrtf(dl*dl + dn*dn + 1e-8f);
    float dtv = fabsf(ts_i - tsj) * (1.f/300.f);
    float ssv = (src_i == srcj) ? 1.f : 0.f;
    float diag = (j == i) ? 1.f : 0.f;
    float vldj = (mask[b*Lc + j] > 0.f) ? 1.f : 0.f;
    float vi   = (mask[b*Lc + i] > 0.f) ? 1.f : 0.f;
    __syncthreads();   // we1s/be1s ready

    // T build: thread owns column j, g selects 32 k rows
    #pragma unroll 8
    for(int kk = 0; kk < 32; kk++){
        int k = g*32 + kk;
        float v = dist*we1s[k] + dtv*we1s[Hc+k] + ssv*we1s[2*Hc+k] + diag*we1s[3*Hc+k] + be1s[k];
        Ts[k*Lc + j] = fmaxf(v, 0.f);
    }
    asm volatile("cp.async.wait_group 0;");
    __syncthreads();   // Ts + W ready

    // GEMM: 4 j (jt..jt+3) x 8 c (c0..c0+7) per thread, both W streams
    int tx = tid & 15, ty2 = tid >> 4;
    int c0 = tx*8, jt = ty2*4;
    unsigned long long aa[16], am[16];
    #pragma unroll
    for(int q = 0; q < 16; q++){ aa[q] = 0ull; am[q] = 0ull; }

    #pragma unroll 2
    for(int k = 0; k < Hc; k++){
        float4 tj = *(const float4*)&Ts[k*Lc + jt];
        unsigned long long tpa = pack2(tj.x, tj.x), tpb = pack2(tj.y, tj.y);
        unsigned long long tpc = pack2(tj.z, tj.z), tpd = pack2(tj.w, tj.w);
        {
            float4 a0 = *(const float4*)&Wa[k*Hc + c0];
            float4 a1 = *(const float4*)&Wa[k*Hc + c0 + 4];
            unsigned long long w0 = pack2(a0.x,a0.y), w1 = pack2(a0.z,a0.w);
            unsigned long long w2 = pack2(a1.x,a1.y), w3 = pack2(a1.z,a1.w);
            fma2(aa[0],tpa,w0); fma2(aa[1],tpa,w1); fma2(aa[2],tpa,w2); fma2(aa[3],tpa,w3);
            fma2(aa[4],tpb,w0); fma2(aa[5],tpb,w1); fma2(aa[6],tpb,w2); fma2(aa[7],tpb,w3);
            fma2(aa[8],tpc,w0); fma2(aa[9],tpc,w1); fma2(aa[10],tpc,w2); fma2(aa[11],tpc,w3);
            fma2(aa[12],tpd,w0); fma2(aa[13],tpd,w1); fma2(aa[14],tpd,w2); fma2(aa[15],tpd,w3);
        }
        {
            float4 m0 = *(const float4*)&Wm[k*Hc + c0];
            float4 m1 = *(const float4*)&Wm[k*Hc + c0 + 4];
            unsigned long long w0 = pack2(m0.x,m0.y), w1 = pack2(m0.z,m0.w);
            unsigned long long w2 = pack2(m1.x,m1.y), w3 = pack2(m1.z,m1.w);
            fma2(am[0],tpa,w0); fma2(am[1],tpa,w1); fma2(am[2],tpa,w2); fma2(am[3],tpa,w3);
            fma2(am[4],tpb,w0); fma2(am[5],tpb,w1); fma2(am[6],tpb,w2); fma2(am[7],tpb,w3);
            fma2(am[8],tpc,w0); fma2(am[9],tpc,w1); fma2(am[10],tpc,w2); fma2(am[11],tpc,w3);
            fma2(am[12],tpd,w0); fma2(am[13],tpd,w1); fma2(am[14],tpd,w2); fma2(am[15],tpd,w3);
        }
    }

    // attention epilogue
    const float* dab = g_da + (size_t)b*Lc*Hc;
    #pragma unroll
    for(int r = 0; r < 4; r++){
        int jj = jt + r;
        float4 d0 = *(const float4*)&dab[(size_t)jj*Hc + c0];
        float4 d1 = *(const float4*)&dab[(size_t)jj*Hc + c0 + 4];
        float u0,u1,u2,u3,u4,u5,u6,u7;
        unpack2(aa[r*4+0], u0, u1); unpack2(aa[r*4+1], u2, u3);
        unpack2(aa[r*4+2], u4, u5); unpack2(aa[r*4+3], u6, u7);
        float s = 0.f;
        s += wa2s[c0+0]*tanhf(sab[c0+0] + d0.x + u0);
        s += wa2s[c0+1]*tanhf(sab[c0+1] + d0.y + u1);
        s += wa2s[c0+2]*tanhf(sab[c0+2] + d0.z + u2);
        s += wa2s[c0+3]*tanhf(sab[c0+3] + d0.w + u3);
        s += wa2s[c0+4]*tanhf(sab[c0+4] + d1.x + u4);
        s += wa2s[c0+5]*tanhf(sab[c0+5] + d1.y + u5);
        s += wa2s[c0+6]*tanhf(sab[c0+6] + d1.z + u6);
        s += wa2s[c0+7]*tanhf(sab[c0+7] + d1.w + u7);
        #pragma unroll
        for(int m = 8; m > 0; m >>= 1) s += __shfl_xor_sync(0xffffffffu, s, m);
        if(tx == 0) att[jj] = s;
    }
    __syncthreads();

    // softmax over j (first 128 threads)
    const float inv = 0.088388347648318440550f;   // 1/sqrt(128)
    float sc = -1e9f, e = 0.f;
    if(tid < 128){
        float a = (att[tid] + ba2[l]) * inv;
        bool ok = (vldj > 0.f) && (vi > 0.f);
        sc = ok ? a : -1e9f;
        float m = sc;
        #pragma unroll
        for(int s2 = 16; s2 > 0; s2 >>= 1) m = fmaxf(m, __shfl_xor_sync(0xffffffffu, m, s2));
        if((tid & 31) == 0) red[tid >> 5] = m;
    }
    __syncthreads();
    float bmax = fmaxf(fmaxf(red[0], red[1]), fmaxf(red[2], red[3]));
    if(tid < 128){
        e = expf(sc - bmax);
        float s2 = e;
        #pragma unroll
        for(int m = 16; m > 0; m >>= 1) s2 += __shfl_xor_sync(0xffffffffu, s2, m);
        if((tid & 31) == 0) red[4 + (tid >> 5)] = s2;
    }
    __syncthreads();
    if(tid < 128){
        float tot = red[4]+red[5]+red[6]+red[7];
        wsoft[tid] = e / tot;
    }
    __syncthreads();

    // message epilogue: weighted relu aggregation
    float ag8[8];
    #pragma unroll
    for(int p = 0; p < 8; p++) ag8[p] = 0.f;
    #pragma unroll
    for(int r = 0; r < 4; r++){
        float wj = wsoft[jt + r];
        float u0,u1,u2,u3,u4,u5,u6,u7;
        unpack2(am[r*4+0], u0, u1); unpack2(am[r*4+1], u2, u3);
        unpack2(am[r*4+2], u4, u5); unpack2(am[r*4+3], u6, u7);
        ag8[0] += wj * fmaxf(smb[c0+0] + u0, 0.f);
        ag8[1] += wj * fmaxf(smb[c0+1] + u1, 0.f);
        ag8[2] += wj * fmaxf(smb[c0+2] + u2, 0.f);
        ag8[3] += wj * fmaxf(smb[c0+3] + u3, 0.f);
        ag8[4] += wj * fmaxf(smb[c0+4] + u4, 0.f);
        ag8[5] += wj * fmaxf(smb[c0+5] + u5, 0.f);
        ag8[6] += wj * fmaxf(smb[c0+6] + u6, 0.f);
        ag8[7] += wj * fmaxf(smb[c0+7] + u7, 0.f);
    }
    // reduce over the 32 j-tile groups (reuse Ts region)
    float* su = dsm;
    #pragma unroll
    for(int p = 0; p < 8; p++) su[ty2*Hc + c0 + p] = ag8[p];
    __syncthreads();
    if(tid < 128){
        float s = 0.f;
        #pragma unroll 8
        for(int t = 0; t < 32; t++) s += su[t*Hc + tid];
        g_aggpre[(size_t)bi*Hc + tid] = s;
    }
}

// ---------------- epilogue per 16 rows: agg@Wm2, out MLP, residual+LN, next-layer sa/da/sm ----------------
__global__ __launch_bounds__(256)
void k_post2(int l, int has_next, const float* __restrict__ mask,
             const float* __restrict__ Wm2, const float* __restrict__ bm2,
             const float* __restrict__ Wo1, const float* __restrict__ bo1,
             const float* __restrict__ Wo2, const float* __restrict__ bo2,
             const float* __restrict__ lng, const float* __restrict__ lnb,
             const float* __restrict__ Wa1, const float* __restrict__ Wm1){
    int row0 = blockIdx.x * 16;
    int tid = threadIdx.x;
    int c = tid & 127, ty = tid >> 7;
    __shared__ float hs[16*Hc], as_[16*Hc], ag[16*Hc], op1[16*Hc];
    __shared__ float mu[16], rsd[16], vmsh[16];

    #pragma unroll
    for(int q = 0; q < 8; q++){
        int idx = q*256 + tid;
        hs[idx]  = g_h[(size_t)row0*Hc + idx];
        as_[idx] = g_aggpre[(size_t)row0*Hc + idx];
    }
    if(tid < 16) vmsh[tid] = mask[row0 + tid] > 0.f ? 1.f : 0.f;
    __syncthreads();

    float acc[8];
    // stage 1: agg = aggpre @ Wm2 + bm2
    const float* wm2 = Wm2 + l*Hc*Hc;
    #pragma unroll
    for(int p = 0; p < 8; p++) acc[p] = bm2[l*Hc + c];
    #pragma unroll 4
    for(int k = 0; k < Hc; k++){
        float w = wm2[k*Hc + c];
        #pragma unroll
        for(int p = 0; p < 8; p++) acc[p] += as_[(ty*8+p)*Hc + k] * w;
    }
    #pragma unroll
    for(int p = 0; p < 8; p++) ag[(ty*8+p)*Hc + c] = acc[p];
    __syncthreads();

    // stage 2: op1 = relu(h@Wo1h + agg@Wo1a + bo1)
    const float* wo1h = Wo1 + l*2*Hc*Hc;
    const float* wo1a = wo1h + Hc*Hc;
    #pragma unroll
    for(int p = 0; p < 8; p++) acc[p] = bo1[l*Hc + c];
    #pragma unroll 4
    for(int k = 0; k < Hc; k++){
        float w1 = wo1h[k*Hc + c], w2 = wo1a[k*Hc + c];
        #pragma unroll
        for(int p = 0; p < 8; p++)
            acc[p] += hs[(ty*8+p)*Hc + k]*w1 + ag[(ty*8+p)*Hc + k]*w2;
    }
    #pragma unroll
    for(int p = 0; p < 8; p++) op1[(ty*8+p)*Hc + c] = fmaxf(acc[p], 0.f);
    __syncthreads();

    // stage 3: o = op1@Wo2 + bo2; x = h + o  (store x into ag)
    const float* wo2 = Wo2 + l*Hc*Hc;
    #pragma unroll
    for(int p = 0; p < 8; p++) acc[p] = bo2[l*Hc + c];
    #pragma unroll 4
    for(int k = 0; k < Hc; k++){
        float w = wo2[k*Hc + c];
        #pragma unroll
        for(int p = 0; p < 8; p++) acc[p] += op1[(ty*8+p)*Hc + k] * w;
    }
    #pragma unroll
    for(int p = 0; p < 8; p++){
        int r = ty*8 + p;
        ag[r*Hc + c] = hs[r*Hc + c] + acc[p];
    }
    __syncthreads();

    // LayerNorm per row
    {
        int row = tid >> 4, l16 = tid & 15;
        float s = 0.f, s2 = 0.f;
        #pragma unroll
        for(int q = 0; q < 8; q++){
            float v = ag[row*Hc + l16 + q*16];
            s += v; s2 += v*v;
        }
        #pragma unroll
        for(int m = 8; m > 0; m >>= 1){
            s  += __shfl_xor_sync(0xffffffffu, s, m);
            s2 += __shfl_xor_sync(0xffffffffu, s2, m);
        }
        if(l16 == 0){
            float m_ = s * (1.f/128.f);
            mu[row] = m_;
            rsd[row] = rsqrtf(s2 * (1.f/128.f) - m_*m_ + 1e-5f);
        }
    }
    __syncthreads();
    const float* lg = lng + l*Hc;
    const float* lb = lnb + l*Hc;
    #pragma unroll
    for(int p = 0; p < 8; p++){
        int r = ty*8 + p;
        float x = ag[r*Hc + c];
        float hn = ((x - mu[r]) * rsd[r] * lg[c] + lb[c]) * vmsh[r];
        g_h[(size_t)(row0+r)*Hc + c] = hn;
        hs[r*Hc + c] = hn;
    }

    if(has_next){
        __syncthreads();
        int ln = l + 1;
        const float* was = Wa1 + ln*3*Hc*Hc;
        const float* wad = was + Hc*Hc;
        const float* wms = Wm1 + ln*2*Hc*Hc;
        float aa[8], dd[8], mm[8];
        #pragma unroll
        for(int p = 0; p < 8; p++){ aa[p]=0.f; dd[p]=0.f; mm[p]=0.f; }
        #pragma unroll 4
        for(int k = 0; k < Hc; k++){
            float w1 = was[k*Hc + c], w2 = wad[k*Hc + c], w3 = wms[k*Hc + c];
            #pragma unroll
            for(int p = 0; p < 8; p++){
                float h = hs[(ty*8+p)*Hc + k];
                aa[p] += h*w1; dd[p] += h*w2; mm[p] += h*w3;
            }
        }
        #pragma unroll
        for(int p = 0; p < 8; p++){
            size_t r = (size_t)(row0 + ty*8 + p)*Hc + c;
            g_sa[r] = aa[p]; g_da[r] = dd[p]; g_sm[r] = mm[p];
        }
    }
}

// ---------------- decoder ----------------
__global__ void k_dec(const float* __restrict__ hist, const float* __restrict__ mask,
                      const float* __restrict__ hg, const float* __restrict__ hb,
                      const float* __restrict__ Wh1, const float* __restrict__ bh1,
                      const float* __restrict__ Wh2, const float* __restrict__ bh2,
                      float* __restrict__ out){
    int b = blockIdx.x; int t = threadIdx.x;
    __shared__ float x[136], xn[136], hid[Hc];
    __shared__ float red2[4];
    float mv = mask[b*Lc + t];
    float s = mv;
    #pragma unroll
    for(int sft = 16; sft > 0; sft >>= 1) s += __shfl_xor_sync(0xffffffffu, s, sft);
    if((t & 31) == 0) red2[t >> 5] = s;
    __syncthreads();
    float tot = red2[0]+red2[1]+red2[2]+red2[3];
    int vc = (int)tot;
    vc = min(max(vc, 1), Lc);
    int last = vc - 1;

    if(t < Dc) x[t] = hist[((size_t)b*Lc + last)*Dc + t];
    x[Dc + t] = g_h[((size_t)b*Lc + last)*Hc + t];
    __syncthreads();
    float s1 = x[t] + ((t < 8) ? x[128 + t] : 0.f);
    #pragma unroll
    for(int sft = 16; sft > 0; sft >>= 1) s1 += __shfl_xor_sync(0xffffffffu, s1, sft);
    __syncthreads();
    if((t & 31) == 0) red2[t >> 5] = s1;
    __syncthreads();
    float mu = (red2[0]+red2[1]+red2[2]+red2[3]) * (1.f/136.f);
    float d0 = x[t] - mu;
    float s2 = d0*d0;
    if(t < 8){ float d1 = x[128 + t] - mu; s2 += d1*d1; }
    #pragma unroll
    for(int sft = 16; sft > 0; sft >>= 1) s2 += __shfl_xor_sync(0xffffffffu, s2, sft);
    __syncthreads();
    if((t & 31) == 0) red2[t >> 5] = s2;
    __syncthreads();
    float rs = rsqrtf((red2[0]+red2[1]+red2[2]+red2[3]) * (1.f/136.f) + 1e-5f);
    xn[t] = (x[t] - mu) * rs * hg[t] + hb[t];
    if(t < 8) xn[128 + t] = (x[128 + t] - mu) * rs * hg[128 + t] + hb[128 + t];
    __syncthreads();
    float h_ = bh1[t];
    for(int k = 0; k < 136; k++) h_ += xn[k]*Wh1[k*Hc + t];
    hid[t] = fmaxf(h_, 0.f);
    __syncthreads();
    if(t < 24){
        float p = bh2[t];
        for(int k = 0; k < Hc; k++) p += hid[k]*Wh2[k*24 + t];
        if(isnan(p)) p = 0.f;
        else if(isinf(p)) p = (p > 0.f) ? 1e4f : -1e4f;
        out[b*24 + t] = p;
    }
}

__global__ void k_copyh(float* __restrict__ out){
    int i = blockIdx.x*blockDim.x + threadIdx.x;
    out[384 + i] = g_h[i];
}

// ---------------- launch ----------------
extern "C" void kernel_launch(void* const* d_in, const int* in_sizes, int n_in,
                              void* d_out, int out_size){
    const float* hist = (const float*)d_in[0];
    const float* mask = (const float*)d_in[1];
    const float* Wp   = (const float*)d_in[2];
    const float* bp   = (const float*)d_in[3];
    const float* We1  = (const float*)d_in[4];
    const float* be1  = (const float*)d_in[5];
    const float* We2  = (const float*)d_in[6];
    const float* be2  = (const float*)d_in[7];
    const float* Wa1  = (const float*)d_in[8];
    const float* ba1  = (const float*)d_in[9];
    const float* wa2  = (const float*)d_in[10];
    const float* ba2  = (const float*)d_in[11];
    const float* Wm1  = (const float*)d_in[12];
    const float* bm1  = (const float*)d_in[13];
    const float* Wm2  = (const float*)d_in[14];
    const float* bm2  = (const float*)d_in[15];
    const float* Wo1  = (const float*)d_in[16];
    const float* bo1  = (const float*)d_in[17];
    const float* Wo2  = (const float*)d_in[18];
    const float* bo2  = (const float*)d_in[19];
    const float* lng  = (const float*)d_in[20];
    const float* lnb  = (const float*)d_in[21];
    const float* hg   = (const float*)d_in[22];
    const float* hbv  = (const float*)d_in[23];
    const float* Wh1  = (const float*)d_in[24];
    const float* bh1  = (const float*)d_in[25];
    const float* Wh2  = (const float*)d_in[26];
    const float* bh2  = (const float*)d_in[27];
    float* out = (float*)d_out;

    cudaFuncSetAttribute(k_main2, cudaFuncAttributeMaxDynamicSharedMemorySize, 196608);

    k_ts<<<1, 32>>>(hist);
    k_prepwb<<<NLc*129, Hc>>>(We2, be2, Wa1, Wm1, ba1, bm1);
    k_h0s<<<Bc*Lc/16, 256>>>(hist, mask, Wp, bp, Wa1, Wm1);
    for(int l = 0; l < NLc; l++){
        k_main2<<<Bc*Lc, 512, 196608>>>(l, hist, mask, We1, be1, wa2, ba2);
        k_post2<<<Bc*Lc/16, 256>>>(l, (l+1 < NLc) ? 1 : 0, mask,
                                   Wm2, bm2, Wo1, bo1, Wo2, bo2, lng, lnb, Wa1, Wm1);
    }
    k_dec<<<Bc, Hc>>>(hist, mask, hg, hbv, Wh1, bh1, Wh2, bh2, out);
    if(out_size >= 384 + Bc*Lc*Hc){
        k_copyh<<<(Bc*Lc*Hc)/256, 256>>>(out);
    }
}

// round 3
// speedup vs baseline: 1.5755x; 1.3961x over previous
#include <cuda_runtime.h>
#include <math.h>

#define Bc 16
#define Lc 128
#define Dc 8
#define Hc 128
#define NLc 2

// ---------------- scratch (static device globals; no allocation) ----------------
__device__ __align__(16) float g_ts[Bc*Lc];
__device__ __align__(16) float g_h[Bc*Lc*Hc];
__device__ __align__(16) float g_sa[Bc*Lc*Hc];
__device__ __align__(16) float g_da[Bc*Lc*Hc];
__device__ __align__(16) float g_sm[Bc*Lc*Hc];
__device__ __align__(16) float g_aggpre[Bc*Lc*Hc];
__device__ __align__(16) float g_Wca[NLc*Hc*Hc];
__device__ __align__(16) float g_Wcm[NLc*Hc*Hc];
__device__ __align__(16) float g_ba[NLc*Hc];
__device__ __align__(16) float g_bm[NLc*Hc];

// ---------------- packed f32x2 helpers ----------------
__device__ __forceinline__ void fma2(unsigned long long &acc, unsigned long long a, unsigned long long b){
    asm("fma.rn.f32x2 %0, %1, %2, %0;" : "+l"(acc) : "l"(a), "l"(b));
}
__device__ __forceinline__ unsigned long long pack2(float lo, float hi){
    unsigned long long r; asm("mov.b64 %0, {%1,%2};" : "=l"(r) : "f"(lo), "f"(hi)); return r;
}
__device__ __forceinline__ void unpack2(unsigned long long v, float &lo, float &hi){
    asm("mov.b64 {%0,%1}, %2;" : "=f"(lo), "=f"(hi) : "l"(v));
}
__device__ __forceinline__ void cp16(void* dst_smem, const void* src){
    unsigned sdst = (unsigned)__cvta_generic_to_shared(dst_smem);
    asm volatile("cp.async.cg.shared.global [%0], [%1], 16;" :: "r"(sdst), "l"(src));
}

// ---------------- cumsum of ts ----------------
__global__ void k_ts(const float* __restrict__ hist){
    int b = threadIdx.x;
    if(b < Bc){
        float c = 0.f;
        for(int t = 0; t < Lc; t++){
            float v = hist[(b*Lc+t)*Dc + 5];
            c += fmaxf(v, 0.f);
            g_ts[b*Lc+t] = c;
        }
    }
}

// ---------------- folded weights: Wc = We2 @ Wa1_e / Wm1_e (plus bias rows) ----------------
__global__ void k_prepwb(const float* __restrict__ We2, const float* __restrict__ be2,
                         const float* __restrict__ Wa1, const float* __restrict__ Wm1,
                         const float* __restrict__ ba1, const float* __restrict__ bm1){
    int l = blockIdx.x / 129, kk = blockIdx.x % 129;
    int c = threadIdx.x;
    __shared__ float ws[Hc];
    if(kk < Hc) ws[c] = We2[l*Hc*Hc + kk*Hc + c];
    else        ws[c] = be2[l*Hc + c];
    __syncthreads();
    const float* wa = Wa1 + l*3*Hc*Hc + 2*Hc*Hc;
    const float* wm = Wm1 + l*2*Hc*Hc + Hc*Hc;
    float sa = 0.f, sm = 0.f;
    #pragma unroll 4
    for(int r = 0; r < Hc; r++){ float w = ws[r]; sa += w*wa[r*Hc + c]; sm += w*wm[r*Hc + c]; }
    if(kk < Hc){
        g_Wca[(l*Hc + kk)*Hc + c] = sa;
        g_Wcm[(l*Hc + kk)*Hc + c] = sm;
    } else {
        g_ba[l*Hc + c] = sa + ba1[l*Hc + c];
        g_bm[l*Hc + c] = sm + bm1[l*Hc + c];
    }
}

// ---------------- h0 (16 rows per block) + sa/da/sm for layer 0 ----------------
__global__ __launch_bounds__(256)
void k_h0s(const float* __restrict__ hist, const float* __restrict__ mask,
           const float* __restrict__ Wp, const float* __restrict__ bp,
           const float* __restrict__ Wa1, const float* __restrict__ Wm1){
    int row0 = blockIdx.x * 16;
    int tid = threadIdx.x;
    int c = tid & 127, ty = tid >> 7;
    __shared__ float xs[16*Dc], hs[16*Hc], vmsh[16];
    if(tid < 128) xs[tid] = hist[(size_t)row0*Dc + tid];
    if(tid < 16)  vmsh[tid] = mask[row0 + tid] > 0.f ? 1.f : 0.f;
    __syncthreads();
    float acc[8];
    #pragma unroll
    for(int p = 0; p < 8; p++) acc[p] = bp[c];
    #pragma unroll
    for(int d = 0; d < Dc; d++){
        float w = Wp[d*Hc + c];
        #pragma unroll
        for(int p = 0; p < 8; p++) acc[p] += xs[(ty*8+p)*Dc + d] * w;
    }
    #pragma unroll
    for(int p = 0; p < 8; p++){
        int r = ty*8 + p;
        float h = acc[p] * vmsh[r];
        hs[r*Hc + c] = h;
        g_h[(size_t)(row0+r)*Hc + c] = h;
    }
    __syncthreads();
    const float* was = Wa1;
    const float* wad = was + Hc*Hc;
    const float* wms = Wm1;
    float aa[8], dd[8], mm[8];
    #pragma unroll
    for(int p = 0; p < 8; p++){ aa[p]=0.f; dd[p]=0.f; mm[p]=0.f; }
    #pragma unroll 4
    for(int k = 0; k < Hc; k++){
        float w1 = was[k*Hc + c], w2 = wad[k*Hc + c], w3 = wms[k*Hc + c];
        #pragma unroll
        for(int p = 0; p < 8; p++){
            float h = hs[(ty*8+p)*Hc + k];
            aa[p] += h*w1; dd[p] += h*w2; mm[p] += h*w3;
        }
    }
    #pragma unroll
    for(int p = 0; p < 8; p++){
        size_t r = (size_t)(row0 + ty*8 + p)*Hc + c;
        g_sa[r] = aa[p]; g_da[r] = dd[p]; g_sm[r] = mm[p];
    }
}

// ---------------- main fused kernel: warp-specialized 8jx8c register-blocked GEMMs ----------------
extern __shared__ float dsm[];   // Ts 64KB | Wa 64KB | Wm 64KB

__global__ __launch_bounds__(512, 1)
void k_main3(int l, const float* __restrict__ hist, const float* __restrict__ mask,
             const float* __restrict__ We1, const float* __restrict__ be1,
             const float* __restrict__ wa2, const float* __restrict__ ba2){
    float* Ts = dsm;                 // [k][j]
    float* Wa = dsm + 16384;         // [k][c]
    float* Wm = dsm + 32768;         // [k][c]
    __shared__ float we1s[4*Hc], be1s[Hc], sab[Hc], smb[Hc], wa2s[Hc];
    __shared__ float att[Lc], wsoft[Lc], red[8];

    int bi = blockIdx.x;
    int b = bi >> 7, i = bi & 127;
    int tid = threadIdx.x;
    int j = tid & 127, kg = tid >> 7;

    // async copy both folded W matrices
    const float* gwa = g_Wca + l*Hc*Hc;
    const float* gwm = g_Wcm + l*Hc*Hc;
    #pragma unroll
    for(int q = 0; q < 8; q++){
        cp16(Wa + q*2048 + tid*4, gwa + q*2048 + tid*4);
        cp16(Wm + q*2048 + tid*4, gwm + q*2048 + tid*4);
    }
    asm volatile("cp.async.commit_group;");

    if(tid < 128){
        #pragma unroll
        for(int q = 0; q < 4; q++) we1s[q*Hc + tid] = We1[l*4*Hc + q*Hc + tid];
        be1s[tid] = be1[l*Hc + tid];
        sab[tid]  = g_sa[(size_t)bi*Hc + tid] + g_ba[l*Hc + tid];
        smb[tid]  = g_sm[(size_t)bi*Hc + tid] + g_bm[l*Hc + tid];
        wa2s[tid] = wa2[l*Hc + tid];
    }

    // edge features for this thread's j (j = tid&127)
    const float* hb_ = hist + (size_t)b*Lc*Dc;
    float lat_i = hb_[i*Dc + 0], lon_i = hb_[i*Dc + 1], src_i = hb_[i*Dc + 6];
    float ts_i = g_ts[b*Lc + i];
    float latj = hb_[j*Dc + 0], lonj = hb_[j*Dc + 1], srcj = hb_[j*Dc + 6];
    float tsj = g_ts[b*Lc + j];
    float dl = lat_i - latj, dn = lon_i - lonj;
    float dist = sqrtf(dl*dl + dn*dn + 1e-8f);
    float dtv = fabsf(ts_i - tsj) * (1.f/300.f);
    float ssv = (src_i == srcj) ? 1.f : 0.f;
    float diag = (j == i) ? 1.f : 0.f;
    float vldj = (mask[b*Lc + j] > 0.f) ? 1.f : 0.f;
    float vi   = (mask[b*Lc + i] > 0.f) ? 1.f : 0.f;
    __syncthreads();   // we1s/be1s ready

    // T build: thread owns column j, kg selects 32 k rows
    #pragma unroll 8
    for(int kk = 0; kk < 32; kk++){
        int k = kg*32 + kk;
        float v = dist*we1s[k] + dtv*we1s[Hc+k] + ssv*we1s[2*Hc+k] + diag*we1s[3*Hc+k] + be1s[k];
        Ts[k*Lc + j] = fmaxf(v, 0.f);
    }
    asm volatile("cp.async.wait_group 0;");
    __syncthreads();   // Ts + W ready

    // warp-specialized GEMM: group g (0=attention/Wa, 1=message/Wm)
    // thread: 8 j (jt..jt+7), 8 c ({ca..ca+3, cb..cb+3})
    int g  = tid >> 8;
    int t  = tid & 255;
    int tx = t & 15, ty = t >> 4;
    int jt = ty*8;
    int ca = tx*4, cb = 64 + tx*4;
    const float* Wg = g ? Wm : Wa;

    unsigned long long acc[32];
    #pragma unroll
    for(int q = 0; q < 32; q++) acc[q] = 0ull;

    #pragma unroll 2
    for(int k = 0; k < Hc; k++){
        const float* tr = &Ts[k*Lc + jt];
        float4 t0 = *(const float4*)tr;
        float4 t1 = *(const float4*)(tr + 4);
        const float* wr = &Wg[k*Hc];
        float4 w0 = *(const float4*)(wr + ca);
        float4 w1 = *(const float4*)(wr + cb);
        unsigned long long wp0 = pack2(w0.x,w0.y), wp1 = pack2(w0.z,w0.w);
        unsigned long long wp2 = pack2(w1.x,w1.y), wp3 = pack2(w1.z,w1.w);
        unsigned long long tp;
        tp = pack2(t0.x,t0.x); fma2(acc[0],tp,wp0);  fma2(acc[1],tp,wp1);  fma2(acc[2],tp,wp2);  fma2(acc[3],tp,wp3);
        tp = pack2(t0.y,t0.y); fma2(acc[4],tp,wp0);  fma2(acc[5],tp,wp1);  fma2(acc[6],tp,wp2);  fma2(acc[7],tp,wp3);
        tp = pack2(t0.z,t0.z); fma2(acc[8],tp,wp0);  fma2(acc[9],tp,wp1);  fma2(acc[10],tp,wp2); fma2(acc[11],tp,wp3);
        tp = pack2(t0.w,t0.w); fma2(acc[12],tp,wp0); fma2(acc[13],tp,wp1); fma2(acc[14],tp,wp2); fma2(acc[15],tp,wp3);
        tp = pack2(t1.x,t1.x); fma2(acc[16],tp,wp0); fma2(acc[17],tp,wp1); fma2(acc[18],tp,wp2); fma2(acc[19],tp,wp3);
        tp = pack2(t1.y,t1.y); fma2(acc[20],tp,wp0); fma2(acc[21],tp,wp1); fma2(acc[22],tp,wp2); fma2(acc[23],tp,wp3);
        tp = pack2(t1.z,t1.z); fma2(acc[24],tp,wp0); fma2(acc[25],tp,wp1); fma2(acc[26],tp,wp2); fma2(acc[27],tp,wp3);
        tp = pack2(t1.w,t1.w); fma2(acc[28],tp,wp0); fma2(acc[29],tp,wp1); fma2(acc[30],tp,wp2); fma2(acc[31],tp,wp3);
    }

    // ---------------- attention epilogue (group 0) ----------------
    if(g == 0){
        const float* dab = g_da + (size_t)b*Lc*Hc;
        #pragma unroll
        for(int jj = 0; jj < 8; jj++){
            int jr = jt + jj;
            float4 d0 = *(const float4*)&dab[(size_t)jr*Hc + ca];
            float4 d1 = *(const float4*)&dab[(size_t)jr*Hc + cb];
            float u0,u1,u2,u3,u4,u5,u6,u7;
            unpack2(acc[jj*4+0], u0, u1); unpack2(acc[jj*4+1], u2, u3);
            unpack2(acc[jj*4+2], u4, u5); unpack2(acc[jj*4+3], u6, u7);
            float s = 0.f;
            s += wa2s[ca+0]*tanhf(sab[ca+0] + d0.x + u0);
            s += wa2s[ca+1]*tanhf(sab[ca+1] + d0.y + u1);
            s += wa2s[ca+2]*tanhf(sab[ca+2] + d0.z + u2);
            s += wa2s[ca+3]*tanhf(sab[ca+3] + d0.w + u3);
            s += wa2s[cb+0]*tanhf(sab[cb+0] + d1.x + u4);
            s += wa2s[cb+1]*tanhf(sab[cb+1] + d1.y + u5);
            s += wa2s[cb+2]*tanhf(sab[cb+2] + d1.z + u6);
            s += wa2s[cb+3]*tanhf(sab[cb+3] + d1.w + u7);
            #pragma unroll
            for(int m = 8; m > 0; m >>= 1) s += __shfl_xor_sync(0xffffffffu, s, m);
            if(tx == 0) att[jr] = s;
        }
    }
    __syncthreads();

    // ---------------- softmax over j (first 128 threads) ----------------
    const float inv = 0.088388347648318440550f;   // 1/sqrt(128)
    float sc = -1e9f, e = 0.f;
    if(tid < 128){
        float a = (att[tid] + ba2[l]) * inv;
        bool ok = (vldj > 0.f) && (vi > 0.f);
        sc = ok ? a : -1e9f;
        float m = sc;
        #pragma unroll
        for(int s2 = 16; s2 > 0; s2 >>= 1) m = fmaxf(m, __shfl_xor_sync(0xffffffffu, m, s2));
        if((tid & 31) == 0) red[tid >> 5] = m;
    }
    __syncthreads();
    float bmax = fmaxf(fmaxf(red[0], red[1]), fmaxf(red[2], red[3]));
    if(tid < 128){
        e = expf(sc - bmax);
        float s2 = e;
        #pragma unroll
        for(int m = 16; m > 0; m >>= 1) s2 += __shfl_xor_sync(0xffffffffu, s2, m);
        if((tid & 31) == 0) red[4 + (tid >> 5)] = s2;
    }
    __syncthreads();
    if(tid < 128){
        float tot = red[4]+red[5]+red[6]+red[7];
        wsoft[tid] = e / tot;
    }
    __syncthreads();

    // ---------------- message epilogue (group 1): weighted relu aggregation ----------------
    float* su = dsm;   // 16 rows x 128 c partials (Ts region is dead now)
    if(g == 1){
        float agA[4], agB[4];
        #pragma unroll
        for(int p = 0; p < 4; p++){ agA[p] = 0.f; agB[p] = 0.f; }
        #pragma unroll
        for(int jj = 0; jj < 8; jj++){
            float wj = wsoft[jt + jj];
            float u0,u1,u2,u3,u4,u5,u6,u7;
            unpack2(acc[jj*4+0], u0, u1); unpack2(acc[jj*4+1], u2, u3);
            unpack2(acc[jj*4+2], u4, u5); unpack2(acc[jj*4+3], u6, u7);
            agA[0] += wj * fmaxf(smb[ca+0] + u0, 0.f);
            agA[1] += wj * fmaxf(smb[ca+1] + u1, 0.f);
            agA[2] += wj * fmaxf(smb[ca+2] + u2, 0.f);
            agA[3] += wj * fmaxf(smb[ca+3] + u3, 0.f);
            agB[0] += wj * fmaxf(smb[cb+0] + u4, 0.f);
            agB[1] += wj * fmaxf(smb[cb+1] + u5, 0.f);
            agB[2] += wj * fmaxf(smb[cb+2] + u6, 0.f);
            agB[3] += wj * fmaxf(smb[cb+3] + u7, 0.f);
        }
        #pragma unroll
        for(int p = 0; p < 4; p++){
            su[ty*Hc + ca + p] = agA[p];
            su[ty*Hc + cb + p] = agB[p];
        }
    }
    __syncthreads();
    if(tid < 128){
        float s = 0.f;
        #pragma unroll 4
        for(int t2 = 0; t2 < 16; t2++) s += su[t2*Hc + tid];
        g_aggpre[(size_t)bi*Hc + tid] = s;
    }
}

// ---------------- epilogue per 16 rows ----------------
__global__ __launch_bounds__(256)
void k_post2(int l, int has_next, const float* __restrict__ mask,
             const float* __restrict__ Wm2, const float* __restrict__ bm2,
             const float* __restrict__ Wo1, const float* __restrict__ bo1,
             const float* __restrict__ Wo2, const float* __restrict__ bo2,
             const float* __restrict__ lng, const float* __restrict__ lnb,
             const float* __restrict__ Wa1, const float* __restrict__ Wm1){
    int row0 = blockIdx.x * 16;
    int tid = threadIdx.x;
    int c = tid & 127, ty = tid >> 7;
    __shared__ float hs[16*Hc], as_[16*Hc], ag[16*Hc], op1[16*Hc];
    __shared__ float mu[16], rsd[16], vmsh[16];

    #pragma unroll
    for(int q = 0; q < 8; q++){
        int idx = q*256 + tid;
        hs[idx]  = g_h[(size_t)row0*Hc + idx];
        as_[idx] = g_aggpre[(size_t)row0*Hc + idx];
    }
    if(tid < 16) vmsh[tid] = mask[row0 + tid] > 0.f ? 1.f : 0.f;
    __syncthreads();

    float acc[8];
    const float* wm2 = Wm2 + l*Hc*Hc;
    #pragma unroll
    for(int p = 0; p < 8; p++) acc[p] = bm2[l*Hc + c];
    #pragma unroll 4
    for(int k = 0; k < Hc; k++){
        float w = wm2[k*Hc + c];
        #pragma unroll
        for(int p = 0; p < 8; p++) acc[p] += as_[(ty*8+p)*Hc + k] * w;
    }
    #pragma unroll
    for(int p = 0; p < 8; p++) ag[(ty*8+p)*Hc + c] = acc[p];
    __syncthreads();

    const float* wo1h = Wo1 + l*2*Hc*Hc;
    const float* wo1a = wo1h + Hc*Hc;
    #pragma unroll
    for(int p = 0; p < 8; p++) acc[p] = bo1[l*Hc + c];
    #pragma unroll 4
    for(int k = 0; k < Hc; k++){
        float w1 = wo1h[k*Hc + c], w2 = wo1a[k*Hc + c];
        #pragma unroll
        for(int p = 0; p < 8; p++)
            acc[p] += hs[(ty*8+p)*Hc + k]*w1 + ag[(ty*8+p)*Hc + k]*w2;
    }
    #pragma unroll
    for(int p = 0; p < 8; p++) op1[(ty*8+p)*Hc + c] = fmaxf(acc[p], 0.f);
    __syncthreads();

    const float* wo2 = Wo2 + l*Hc*Hc;
    #pragma unroll
    for(int p = 0; p < 8; p++) acc[p] = bo2[l*Hc + c];
    #pragma unroll 4
    for(int k = 0; k < Hc; k++){
        float w = wo2[k*Hc + c];
        #pragma unroll
        for(int p = 0; p < 8; p++) acc[p] += op1[(ty*8+p)*Hc + k] * w;
    }
    #pragma unroll
    for(int p = 0; p < 8; p++){
        int r = ty*8 + p;
        ag[r*Hc + c] = hs[r*Hc + c] + acc[p];
    }
    __syncthreads();

    {
        int row = tid >> 4, l16 = tid & 15;
        float s = 0.f, s2 = 0.f;
        #pragma unroll
        for(int q = 0; q < 8; q++){
            float v = ag[row*Hc + l16 + q*16];
            s += v; s2 += v*v;
        }
        #pragma unroll
        for(int m = 8; m > 0; m >>= 1){
            s  += __shfl_xor_sync(0xffffffffu, s, m);
            s2 += __shfl_xor_sync(0xffffffffu, s2, m);
        }
        if(l16 == 0){
            float m_ = s * (1.f/128.f);
            mu[row] = m_;
            rsd[row] = rsqrtf(s2 * (1.f/128.f) - m_*m_ + 1e-5f);
        }
    }
    __syncthreads();
    const float* lg = lng + l*Hc;
    const float* lb = lnb + l*Hc;
    #pragma unroll
    for(int p = 0; p < 8; p++){
        int r = ty*8 + p;
        float x = ag[r*Hc + c];
        float hn = ((x - mu[r]) * rsd[r] * lg[c] + lb[c]) * vmsh[r];
        g_h[(size_t)(row0+r)*Hc + c] = hn;
        hs[r*Hc + c] = hn;
    }

    if(has_next){
        __syncthreads();
        int ln = l + 1;
        const float* was = Wa1 + ln*3*Hc*Hc;
        const float* wad = was + Hc*Hc;
        const float* wms = Wm1 + ln*2*Hc*Hc;
        float aa[8], dd[8], mm[8];
        #pragma unroll
        for(int p = 0; p < 8; p++){ aa[p]=0.f; dd[p]=0.f; mm[p]=0.f; }
        #pragma unroll 4
        for(int k = 0; k < Hc; k++){
            float w1 = was[k*Hc + c], w2 = wad[k*Hc + c], w3 = wms[k*Hc + c];
            #pragma unroll
            for(int p = 0; p < 8; p++){
                float h = hs[(ty*8+p)*Hc + k];
                aa[p] += h*w1; dd[p] += h*w2; mm[p] += h*w3;
            }
        }
        #pragma unroll
        for(int p = 0; p < 8; p++){
            size_t r = (size_t)(row0 + ty*8 + p)*Hc + c;
            g_sa[r] = aa[p]; g_da[r] = dd[p]; g_sm[r] = mm[p];
        }
    }
}

// ---------------- decoder ----------------
__global__ void k_dec(const float* __restrict__ hist, const float* __restrict__ mask,
                      const float* __restrict__ hg, const float* __restrict__ hb,
                      const float* __restrict__ Wh1, const float* __restrict__ bh1,
                      const float* __restrict__ Wh2, const float* __restrict__ bh2,
                      float* __restrict__ out){
    int b = blockIdx.x; int t = threadIdx.x;
    __shared__ float x[136], xn[136], hid[Hc];
    __shared__ float red2[4];
    float mv = mask[b*Lc + t];
    float s = mv;
    #pragma unroll
    for(int sft = 16; sft > 0; sft >>= 1) s += __shfl_xor_sync(0xffffffffu, s, sft);
    if((t & 31) == 0) red2[t >> 5] = s;
    __syncthreads();
    float tot = red2[0]+red2[1]+red2[2]+red2[3];
    int vc = (int)tot;
    vc = min(max(vc, 1), Lc);
    int last = vc - 1;

    if(t < Dc) x[t] = hist[((size_t)b*Lc + last)*Dc + t];
    x[Dc + t] = g_h[((size_t)b*Lc + last)*Hc + t];
    __syncthreads();
    float s1 = x[t] + ((t < 8) ? x[128 + t] : 0.f);
    #pragma unroll
    for(int sft = 16; sft > 0; sft >>= 1) s1 += __shfl_xor_sync(0xffffffffu, s1, sft);
    __syncthreads();
    if((t & 31) == 0) red2[t >> 5] = s1;
    __syncthreads();
    float mu = (red2[0]+red2[1]+red2[2]+red2[3]) * (1.f/136.f);
    float d0 = x[t] - mu;
    float s2 = d0*d0;
    if(t < 8){ float d1 = x[128 + t] - mu; s2 += d1*d1; }
    #pragma unroll
    for(int sft = 16; sft > 0; sft >>= 1) s2 += __shfl_xor_sync(0xffffffffu, s2, sft);
    __syncthreads();
    if((t & 31) == 0) red2[t >> 5] = s2;
    __syncthreads();
    float rs = rsqrtf((red2[0]+red2[1]+red2[2]+red2[3]) * (1.f/136.f) + 1e-5f);
    xn[t] = (x[t] - mu) * rs * hg[t] + hb[t];
    if(t < 8) xn[128 + t] = (x[128 + t] - mu) * rs * hg[128 + t] + hb[128 + t];
    __syncthreads();
    float h_ = bh1[t];
    for(int k = 0; k < 136; k++) h_ += xn[k]*Wh1[k*Hc + t];
    hid[t] = fmaxf(h_, 0.f);
    __syncthreads();
    if(t < 24){
        float p = bh2[t];
        for(int k = 0; k < Hc; k++) p += hid[k]*Wh2[k*24 + t];
        if(isnan(p)) p = 0.f;
        else if(isinf(p)) p = (p > 0.f) ? 1e4f : -1e4f;
        out[b*24 + t] = p;
    }
}

__global__ void k_copyh(float* __restrict__ out){
    int i = blockIdx.x*blockDim.x + threadIdx.x;
    out[384 + i] = g_h[i];
}

// ---------------- launch ----------------
extern "C" void kernel_launch(void* const* d_in, const int* in_sizes, int n_in,
                              void* d_out, int out_size){
    const float* hist = (const float*)d_in[0];
    const float* mask = (const float*)d_in[1];
    const float* Wp   = (const float*)d_in[2];
    const float* bp   = (const float*)d_in[3];
    const float* We1  = (const float*)d_in[4];
    const float* be1  = (const float*)d_in[5];
    const float* We2  = (const float*)d_in[6];
    const float* be2  = (const float*)d_in[7];
    const float* Wa1  = (const float*)d_in[8];
    const float* ba1  = (const float*)d_in[9];
    const float* wa2  = (const float*)d_in[10];
    const float* ba2  = (const float*)d_in[11];
    const float* Wm1  = (const float*)d_in[12];
    const float* bm1  = (const float*)d_in[13];
    const float* Wm2  = (const float*)d_in[14];
    const float* bm2  = (const float*)d_in[15];
    const float* Wo1  = (const float*)d_in[16];
    const float* bo1  = (const float*)d_in[17];
    const float* Wo2  = (const float*)d_in[18];
    const float* bo2  = (const float*)d_in[19];
    const float* lng  = (const float*)d_in[20];
    const float* lnb  = (const float*)d_in[21];
    const float* hg   = (const float*)d_in[22];
    const float* hbv  = (const float*)d_in[23];
    const float* Wh1  = (const float*)d_in[24];
    const float* bh1  = (const float*)d_in[25];
    const float* Wh2  = (const float*)d_in[26];
    const float* bh2  = (const float*)d_in[27];
    float* out = (float*)d_out;

    cudaFuncSetAttribute(k_main3, cudaFuncAttributeMaxDynamicSharedMemorySize, 196608);

    k_ts<<<1, 32>>>(hist);
    k_prepwb<<<NLc*129, Hc>>>(We2, be2, Wa1, Wm1, ba1, bm1);
    k_h0s<<<Bc*Lc/16, 256>>>(hist, mask, Wp, bp, Wa1, Wm1);
    for(int l = 0; l < NLc; l++){
        k_main3<<<Bc*Lc, 512, 196608>>>(l, hist, mask, We1, be1, wa2, ba2);
        k_post2<<<Bc*Lc/16, 256>>>(l, (l+1 < NLc) ? 1 : 0, mask,
                                   Wm2, bm2, Wo1, bo1, Wo2, bo2, lng, lnb, Wa1, Wm1);
    }
    k_dec<<<Bc, Hc>>>(hist, mask, hg, hbv, Wh1, bh1, Wh2, bh2, out);
    if(out_size >= 384 + Bc*Lc*Hc){
        k_copyh<<<(Bc*Lc*Hc)/256, 256>>>(out);
    }
}